// round 13
// baseline (speedup 1.0000x reference)
#include <cuda_runtime.h>
#include <math.h>
#include <stdint.h>

// Problem dimensions (fixed by the dataset)
#define B_  2
#define S_  2048
#define D_  2048
#define QH_ 16
#define KH_ 4
#define HD_ 128
#define M_ROWS (B_ * S_)   // 4096

// ---------------------------------------------------------------------------
// Scratch (no allocations allowed -> __device__ globals)
// ---------------------------------------------------------------------------
__device__ float g_q[B_ * S_ * QH_ * HD_];   // 8M floats (pair-permuted cols)
__device__ float g_k[B_ * S_ * KH_ * HD_];   // 2M (pair-permuted cols)
__device__ float g_v[B_ * S_ * KH_ * HD_];   // 2M (natural)
__device__ float g_att[B_ * S_ * QH_ * HD_]; // 8M
__device__ float g_xr[B_ * S_ * D_];         // 8M  (tf32-rounded x)
__device__ float g_wq[QH_ * D_ * HD_];       // 4M  (tf32-rounded weights)
__device__ float g_wk[KH_ * D_ * HD_];       // 1M
__device__ float g_wv[KH_ * D_ * HD_];       // 1M
__device__ float g_wo[QH_ * HD_ * D_];       // 4M
__device__ float2 g_rt[S_ * 64];             // sin/cos table

// ---------------------------------------------------------------------------
// TF32 / cp.async helpers
// ---------------------------------------------------------------------------
__device__ __forceinline__ uint32_t f2tf32(float f) {
    uint32_t u;
    asm("cvt.rna.tf32.f32 %0, %1;" : "=r"(u) : "f"(f));
    return u;
}

__device__ __forceinline__ void mma_tf32(float* c, const uint32_t* a, const uint32_t* b) {
    asm volatile(
        "mma.sync.aligned.m16n8k8.row.col.f32.tf32.tf32.f32 "
        "{%0,%1,%2,%3}, {%4,%5,%6,%7}, {%8,%9}, {%0,%1,%2,%3};\n"
        : "+f"(c[0]), "+f"(c[1]), "+f"(c[2]), "+f"(c[3])
        : "r"(a[0]), "r"(a[1]), "r"(a[2]), "r"(a[3]), "r"(b[0]), "r"(b[1]));
}

__device__ __forceinline__ void cp_async16(void* sptr, const void* gptr) {
    uint32_t sa = (uint32_t)__cvta_generic_to_shared(sptr);
    asm volatile("cp.async.cg.shared.global [%0], [%1], 16;\n" :: "r"(sa), "l"(gptr));
}
#define CP_COMMIT() asm volatile("cp.async.commit_group;\n" ::: "memory")
#define CP_WAIT1()  asm volatile("cp.async.wait_group 1;\n" ::: "memory")

// pair permutation within an 8-group: j -> 2*(j&3) | (j>>2)
__device__ __forceinline__ int perm8(int j) { return (((j) & 3) << 1) | (((j) >> 2) & 1); }

// ---------------------------------------------------------------------------
// Elementwise tf32 rounding pass (vectorized)
// ---------------------------------------------------------------------------
__global__ void round_tf32_kernel(float* __restrict__ dst, const float* __restrict__ src,
                                  int n4) {
    int i = blockIdx.x * blockDim.x + threadIdx.x;
    if (i >= n4) return;
    float4 v = ((const float4*)src)[i];
    uint4 t = make_uint4(f2tf32(v.x), f2tf32(v.y), f2tf32(v.z), f2tf32(v.w));
    ((uint4*)dst)[i] = t;
}

// ---------------------------------------------------------------------------
// Pipelined TF32 GEMM body. CTA tile 128x128, BK=32, 3-stage cp.async.
// 256 threads = 8 warps (2m x 4n), warp tile 64x32, m16n8k8.
// acc = 64 regs/thread -> fits 2 CTAs/SM with __launch_bounds__(256, 2).
// PERMC: epilogue stores columns pair-permuted within 8-groups (Q/K outputs).
// ROUNDC: epilogue rounds C to tf32 (V output).
// ---------------------------------------------------------------------------
#define GSTAGES 3
#define ASTG (128 * 36)
#define BSTG (32 * 136)
#define STG_WORDS (ASTG + BSTG)
#define GEMM_SMEM (GSTAGES * STG_WORDS * 4)

template <bool PERMC, bool ROUNDC>
__device__ __forceinline__ void gemm_body(const float* __restrict__ A,
                                          const float* __restrict__ W,
                                          float* __restrict__ C,
                                          int K, int ldc, int wld,
                                          int brow, int ccol, float* smem) {
    const int tid  = threadIdx.x;
    const int lane = tid & 31;
    const int wid  = tid >> 5;
    const int warpm = wid >> 2;        // 0..1 (64-row slices)
    const int warpn = wid & 3;         // 0..3 (32-col slices)
    const int g = lane >> 2;
    const int q = lane & 3;

    const int am  = tid >> 3;          // 0..31
    const int ak4 = (tid & 7) << 2;    // 0..28
    const int bk  = tid >> 5;          // 0..7
    const int bn4 = (tid & 31) << 2;   // 0..124
    const int NITER = K >> 5;

    const float* Abase = A + (size_t)(brow + am) * K + ak4;

    float acc[4][4][4];
#pragma unroll
    for (int mt = 0; mt < 4; mt++)
#pragma unroll
        for (int nt = 0; nt < 4; nt++)
#pragma unroll
            for (int i = 0; i < 4; i++) acc[mt][nt][i] = 0.f;

    auto issue_tile = [&](int t) {
        float* As = smem + (t % GSTAGES) * STG_WORDS;
        float* Bs = As + ASTG;
        const int k0 = t << 5;
        const float* ap = Abase + k0;
#pragma unroll
        for (int p = 0; p < 4; p++)
            cp_async16(As + (am + 32 * p) * 36 + ak4, ap + (size_t)(32 * p) * K);
        const float* wp = W + (size_t)(k0 + bk) * wld + bn4;
#pragma unroll
        for (int p = 0; p < 4; p++)
            cp_async16(Bs + (bk + 8 * p) * 136 + bn4, wp + (size_t)(8 * p) * wld);
    };

    issue_tile(0); CP_COMMIT();
    issue_tile(1); CP_COMMIT();

    for (int i = 0; i < NITER; i++) {
        CP_WAIT1();
        __syncthreads();
        if (i + 2 < NITER) issue_tile(i + 2);
        CP_COMMIT();

        const uint32_t* As = (const uint32_t*)(smem + (i % GSTAGES) * STG_WORDS);
        const uint32_t* Bs = As + ASTG;

#pragma unroll
        for (int kk = 0; kk < 4; kk++) {
            const int kc = kk * 8;
            uint32_t af[4][4];
            uint32_t bf[4][2];
#pragma unroll
            for (int mt = 0; mt < 4; mt++) {
                int r = warpm * 64 + mt * 16 + g;
                af[mt][0] = As[r * 36 + kc + q];
                af[mt][1] = As[(r + 8) * 36 + kc + q];
                af[mt][2] = As[r * 36 + kc + q + 4];
                af[mt][3] = As[(r + 8) * 36 + kc + q + 4];
            }
#pragma unroll
            for (int nt = 0; nt < 4; nt++) {
                int c = warpn * 32 + nt * 8 + g;
                bf[nt][0] = Bs[(kc + q) * 136 + c];
                bf[nt][1] = Bs[(kc + q + 4) * 136 + c];
            }
#pragma unroll
            for (int mt = 0; mt < 4; mt++)
#pragma unroll
                for (int nt = 0; nt < 4; nt++)
                    mma_tf32(acc[mt][nt], af[mt], bf[nt]);
        }
    }

    // ---- epilogue ----
    const int p0 = perm8(2 * q);
    const int p1 = perm8(2 * q + 1);
#pragma unroll
    for (int mt = 0; mt < 4; mt++) {
        int r = brow + warpm * 64 + mt * 16 + g;
#pragma unroll
        for (int nt = 0; nt < 4; nt++) {
            if (PERMC) {
                int cb = ccol + warpn * 32 + nt * 8;
                C[(size_t)r * ldc + cb + p0] = acc[mt][nt][0];
                C[(size_t)r * ldc + cb + p1] = acc[mt][nt][1];
                C[(size_t)(r + 8) * ldc + cb + p0] = acc[mt][nt][2];
                C[(size_t)(r + 8) * ldc + cb + p1] = acc[mt][nt][3];
            } else {
                int c = ccol + warpn * 32 + nt * 8 + 2 * q;
                if (ROUNDC) {
                    uint2 c0 = make_uint2(f2tf32(acc[mt][nt][0]), f2tf32(acc[mt][nt][1]));
                    uint2 c1 = make_uint2(f2tf32(acc[mt][nt][2]), f2tf32(acc[mt][nt][3]));
                    *(uint2*)&C[(size_t)r * ldc + c] = c0;
                    *(uint2*)&C[(size_t)(r + 8) * ldc + c] = c1;
                } else {
                    *(float2*)&C[(size_t)r * ldc + c] = make_float2(acc[mt][nt][0], acc[mt][nt][1]);
                    *(float2*)&C[(size_t)(r + 8) * ldc + c] = make_float2(acc[mt][nt][2], acc[mt][nt][3]);
                }
            }
        }
    }
}

// Merged QKV projection: grid (24 head blocks, 32 row-blocks)
__global__ __launch_bounds__(256, 2) void qkv_proj(const float* __restrict__ x,
                                                   const float* __restrict__ Wq,
                                                   const float* __restrict__ Wk,
                                                   const float* __restrict__ Wv,
                                                   float* __restrict__ qo,
                                                   float* __restrict__ ko,
                                                   float* __restrict__ vo) {
    extern __shared__ float sm_f[];
    const int h = blockIdx.x;
    const int brow = blockIdx.y * 128;
    if (h < QH_) {
        gemm_body<true, false>(x, Wq + (size_t)h * D_ * HD_, qo,
                               D_, QH_ * HD_, HD_, brow, h * HD_, sm_f);
    } else if (h < QH_ + KH_) {
        int p = h - QH_;
        gemm_body<true, false>(x, Wk + (size_t)p * D_ * HD_, ko,
                               D_, KH_ * HD_, HD_, brow, p * HD_, sm_f);
    } else {
        int p = h - QH_ - KH_;
        gemm_body<false, true>(x, Wv + (size_t)p * D_ * HD_, vo,
                               D_, KH_ * HD_, HD_, brow, p * HD_, sm_f);
    }
}

// Output projection: grid (16 col-blocks of 128, 32 row-blocks)
__global__ __launch_bounds__(256, 2) void o_proj(const float* __restrict__ att,
                                                 const float* __restrict__ Wo,
                                                 float* __restrict__ out) {
    extern __shared__ float sm_f[];
    const int bcol = blockIdx.x * 128;
    const int brow = blockIdx.y * 128;
    gemm_body<false, false>(att, Wo + bcol, out, QH_ * HD_, D_, D_, brow, bcol, sm_f);
}

// ---------------------------------------------------------------------------
// sin/cos table: rt[s][hp] = (cos(ang), sin(ang)) — bit-identical ops
// ---------------------------------------------------------------------------
__global__ void sincos_kernel(float2* __restrict__ rt, const int* __restrict__ positions) {
    int i = blockIdx.x * blockDim.x + threadIdx.x;
    if (i >= S_ * 64) return;
    int hp = i & 63;
    int s  = i >> 6;
    float pos = (float)positions[s];
    float ts  = expf(((float)hp / 64.f) * 9.21034037197618f /* ln(1e4) */);
    float ang = pos / ts;
    rt[i] = make_float2(cosf(ang), sinf(ang));
}

// ---------------------------------------------------------------------------
// RoPE (in-place) on pair-permuted [B, S, NH, 128]; folds `scale` into the
// rotation (Q gets 1/sqrt(d), K gets 1). Each thread owns its 2 physical slots.
// ---------------------------------------------------------------------------
__global__ void rope_kernel(float* __restrict__ x, const float2* __restrict__ rt,
                            int NH, int total, float scale) {
    int i = blockIdx.x * blockDim.x + threadIdx.x;
    if (i >= total) return;
    int hp = i & 63;
    int rest = i >> 6;
    int nh = rest % NH;
    int s  = (rest / NH) % S_;
    int b  = rest / (NH * S_);

    float2 cs2 = rt[s * 64 + hp];
    float cs = cs2.x * scale;
    float sn = cs2.y * scale;

    int p = (hp & ~7) | perm8(hp & 7);
    size_t base = ((size_t)(b * S_ + s) * NH + nh) * HD_;
    float x1 = x[base + p];
    float x2 = x[base + p + 64];
    x[base + p]      = __uint_as_float(f2tf32(x1 * cs - x2 * sn));
    x[base + p + 64] = __uint_as_float(f2tf32(x2 * cs + x1 * sn));
}

// ---------------------------------------------------------------------------
// Flash attention v3 (unchanged from R10, passing @ ~380us)
// ---------------------------------------------------------------------------
#define QS2 136
#define KS2 136
#define VS2 136
#define PS2 72
#define KTILE_W (64 * KS2)

#define F2_SMEM ((128 * QS2 + 2 * KTILE_W + 64 * VS2 + 128 * PS2 + 512 + 512) * 4)

__global__ __launch_bounds__(512) void flash_tc2(const float* __restrict__ Q,
                                                 const float* __restrict__ K,
                                                 const float* __restrict__ V,
                                                 float* __restrict__ O) {
    extern __shared__ uint32_t sm_u[];
    uint32_t* Qs = sm_u;                    // [128][136] pair layout
    uint32_t* Kb = Qs + 128 * QS2;          // 2 x [64][136] pair layout
    uint32_t* Vs = Kb + 2 * KTILE_W;        // [64][136] natural
    uint32_t* Ps = Vs + 64 * VS2;           // [128][72] pair layout
    float* smax  = (float*)(Ps + 128 * PS2);   // [4][128]
    float* ssum  = smax + 512;                 // [4][128]

    const int tid  = threadIdx.x;
    const int lane = tid & 31;
    const int wid  = tid >> 5;
    const int warpm = wid >> 2;
    const int warpn = wid & 3;
    const int g = lane >> 2;
    const int q = lane & 3;

    const int mblk = gridDim.x - 1 - blockIdx.x;
    const int bq = blockIdx.y;
    const int b  = bq / QH_;
    const int qh = bq % QH_;
    const int kvh = qh / (QH_ / KH_);

    float rmr[2][2], rlr[2][2];
#pragma unroll
    for (int mt = 0; mt < 2; mt++)
#pragma unroll
        for (int h = 0; h < 2; h++) { rmr[mt][h] = -INFINITY; rlr[mt][h] = 0.f; }

    float o[2][4][4];
#pragma unroll
    for (int mt = 0; mt < 2; mt++)
#pragma unroll
        for (int nt = 0; nt < 4; nt++)
#pragma unroll
            for (int i = 0; i < 4; i++) o[mt][nt][i] = 0.f;

    const int row_base = warpm * 32 + g;
    const int qkcol_base = warpn * 16 + 2 * q;
    const int NIT = 2 * mblk + 2;

    auto issueQ = [&]() {
        for (int idx = tid; idx < 128 * 32; idx += 512) {
            int r  = idx >> 5;
            int c4 = (idx & 31) << 2;
            cp_async16(Qs + r * QS2 + c4,
                       Q + ((size_t)(b * S_ + mblk * 128 + r) * QH_ + qh) * HD_ + c4);
        }
    };
    auto issueK = [&](int n) {
        uint32_t* kd = Kb + (n & 1) * KTILE_W;
        for (int idx = tid; idx < 64 * 32; idx += 512) {
            int r  = idx >> 5;
            int c4 = (idx & 31) << 2;
            cp_async16(kd + r * KS2 + c4,
                       K + ((size_t)(b * S_ + n * 64 + r) * KH_ + kvh) * HD_ + c4);
        }
    };
    auto issueV = [&](int n) {
        for (int idx = tid; idx < 64 * 32; idx += 512) {
            int r  = idx >> 5;
            int c4 = (idx & 31) << 2;
            cp_async16(Vs + r * VS2 + c4,
                       V + ((size_t)(b * S_ + n * 64 + r) * KH_ + kvh) * HD_ + c4);
        }
    };

    issueQ(); issueK(0); issueV(0); CP_COMMIT();

    for (int n = 0; n < NIT; n++) {
        if (n + 1 < NIT) issueK(n + 1);
        CP_COMMIT();
        CP_WAIT1();
        __syncthreads();           // A: Q(first), K(n), V(n) ready

        const uint32_t* Kst = Kb + (n & 1) * KTILE_W;

        // ---- QK^T (scores pre-scaled via Q) ----
        float s[2][2][4];
#pragma unroll
        for (int mt = 0; mt < 2; mt++)
#pragma unroll
            for (int nt = 0; nt < 2; nt++)
#pragma unroll
                for (int i = 0; i < 4; i++) s[mt][nt][i] = 0.f;

#pragma unroll
        for (int ks = 0; ks < 16; ks++) {
            const int kc = ks * 8;
            uint32_t af[2][4], bf[2][2];
#pragma unroll
            for (int mt = 0; mt < 2; mt++) {
                int r = warpm * 32 + mt * 16 + g;
                uint2 a0 = *(const uint2*)&Qs[r * QS2 + kc + q * 2];
                uint2 a1 = *(const uint2*)&Qs[(r + 8) * QS2 + kc + q * 2];
                af[mt][0] = a0.x; af[mt][2] = a0.y;
                af[mt][1] = a1.x; af[mt][3] = a1.y;
            }
#pragma unroll
            for (int nt = 0; nt < 2; nt++) {
                int c = warpn * 16 + nt * 8 + g;
                uint2 b2 = *(const uint2*)&Kst[c * KS2 + kc + q * 2];
                bf[nt][0] = b2.x;
                bf[nt][1] = b2.y;
            }
#pragma unroll
            for (int mt = 0; mt < 2; mt++)
#pragma unroll
                for (int nt = 0; nt < 2; nt++)
                    mma_tf32(s[mt][nt], af[mt], bf[nt]);
        }

        // ---- causal mask (only on the diagonal pair of tiles) ----
        if (n >= 2 * mblk) {
            const int gr_base = mblk * 128 + row_base;
            const int gc_base = n * 64 + qkcol_base;
#pragma unroll
            for (int mt = 0; mt < 2; mt++) {
                int gr0 = gr_base + mt * 16;
                int gr1 = gr0 + 8;
#pragma unroll
                for (int nt = 0; nt < 2; nt++) {
                    int gc0 = gc_base + nt * 8;
                    int gc1 = gc0 + 1;
                    if (gc0 > gr0) s[mt][nt][0] = -1e9f;
                    if (gc1 > gr0) s[mt][nt][1] = -1e9f;
                    if (gc0 > gr1) s[mt][nt][2] = -1e9f;
                    if (gc1 > gr1) s[mt][nt][3] = -1e9f;
                }
            }
        }

        // ---- partial row max -> smax ----
#pragma unroll
        for (int mt = 0; mt < 2; mt++)
#pragma unroll
            for (int h = 0; h < 2; h++) {
                float pm = fmaxf(fmaxf(s[mt][0][2 * h], s[mt][0][2 * h + 1]),
                                 fmaxf(s[mt][1][2 * h], s[mt][1][2 * h + 1]));
                pm = fmaxf(pm, __shfl_xor_sync(0xFFFFFFFF, pm, 1));
                pm = fmaxf(pm, __shfl_xor_sync(0xFFFFFFFF, pm, 2));
                if (q == 0) smax[warpn * 128 + row_base + mt * 16 + 8 * h] = pm;
            }
        __syncthreads();           // B: smax complete

        // ---- m update (registers), exp, P store, partial sums ----
        const int poff0 = perm8(2 * q);
        const int poff1 = perm8(2 * q + 1);
        float corr[2][2];
#pragma unroll
        for (int mt = 0; mt < 2; mt++)
#pragma unroll
            for (int h = 0; h < 2; h++) {
                int row = row_base + mt * 16 + 8 * h;
                float m_tile = fmaxf(fmaxf(smax[row], smax[128 + row]),
                                     fmaxf(smax[256 + row], smax[384 + row]));
                float m_old = rmr[mt][h];
                float m_new = fmaxf(m_old, m_tile);
                corr[mt][h] = __expf(m_old - m_new);
                rmr[mt][h] = m_new;

                float psum = 0.f;
#pragma unroll
                for (int nt = 0; nt < 2; nt++) {
                    float p0 = __expf(s[mt][nt][2 * h] - m_new);
                    float p1 = __expf(s[mt][nt][2 * h + 1] - m_new);
                    psum += p0 + p1;
                    uint32_t* pb = Ps + row * PS2 + (warpn * 2 + nt) * 8;
                    pb[poff0] = f2tf32(p0);
                    pb[poff1] = f2tf32(p1);
                }
                psum += __shfl_xor_sync(0xFFFFFFFF, psum, 1);
                psum += __shfl_xor_sync(0xFFFFFFFF, psum, 2);
                if (q == 0) ssum[warpn * 128 + row] = psum;
            }
        __syncthreads();           // C: Ps + ssum complete

        // ---- l update (registers) ----
#pragma unroll
        for (int mt = 0; mt < 2; mt++)
#pragma unroll
            for (int h = 0; h < 2; h++) {
                int row = row_base + mt * 16 + 8 * h;
                float ts = ssum[row] + ssum[128 + row] + ssum[256 + row] + ssum[384 + row];
                rlr[mt][h] = rlr[mt][h] * corr[mt][h] + ts;
            }

        // ---- rescale O, then PV mma ----
#pragma unroll
        for (int mt = 0; mt < 2; mt++)
#pragma unroll
            for (int nt = 0; nt < 4; nt++) {
                o[mt][nt][0] *= corr[mt][0];
                o[mt][nt][1] *= corr[mt][0];
                o[mt][nt][2] *= corr[mt][1];
                o[mt][nt][3] *= corr[mt][1];
            }

#pragma unroll
        for (int ks = 0; ks < 8; ks++) {
            const int kc = ks * 8;
            uint32_t af[2][4], bf[4][2];
#pragma unroll
            for (int mt = 0; mt < 2; mt++) {
                int r = warpm * 32 + mt * 16 + g;
                uint2 a0 = *(const uint2*)&Ps[r * PS2 + kc + q * 2];
                uint2 a1 = *(const uint2*)&Ps[(r + 8) * PS2 + kc + q * 2];
                af[mt][0] = a0.x; af[mt][2] = a0.y;
                af[mt][1] = a1.x; af[mt][3] = a1.y;
            }
#pragma unroll
            for (int nt = 0; nt < 4; nt++) {
                int c = warpn * 32 + nt * 8 + g;
                bf[nt][0] = Vs[(kc + q) * VS2 + c];
                bf[nt][1] = Vs[(kc + q + 4) * VS2 + c];
            }
#pragma unroll
            for (int mt = 0; mt < 2; mt++)
#pragma unroll
                for (int nt = 0; nt < 4; nt++)
                    mma_tf32(o[mt][nt], af[mt], bf[nt]);
        }

        __syncthreads();           // D: all warps done with Ps/Vs
        if (n + 1 < NIT) issueV(n + 1);
        CP_COMMIT();
    }

    // ---- epilogue: normalize + round to tf32 (o_proj consumes raw) ----
#pragma unroll
    for (int mt = 0; mt < 2; mt++) {
        float inv0 = 1.0f / rlr[mt][0];
        float inv1 = 1.0f / rlr[mt][1];
        int s0 = mblk * 128 + row_base + mt * 16;
#pragma unroll
        for (int nt = 0; nt < 4; nt++) {
            int col = warpn * 32 + nt * 8 + 2 * q;
            float* op0 = O + ((size_t)(b * S_ + s0) * QH_ + qh) * HD_ + col;
            float* op1 = O + ((size_t)(b * S_ + s0 + 8) * QH_ + qh) * HD_ + col;
            *(uint2*)op0 = make_uint2(f2tf32(o[mt][nt][0] * inv0), f2tf32(o[mt][nt][1] * inv0));
            *(uint2*)op1 = make_uint2(f2tf32(o[mt][nt][2] * inv1), f2tf32(o[mt][nt][3] * inv1));
        }
    }
}

// ---------------------------------------------------------------------------
// Launch
// ---------------------------------------------------------------------------
extern "C" void kernel_launch(void* const* d_in, const int* in_sizes, int n_in,
                              void* d_out, int out_size) {
    const float* x         = (const float*)d_in[0];
    const int*   positions = (const int*)d_in[1];
    const float* Wq        = (const float*)d_in[2];
    const float* Wk        = (const float*)d_in[3];
    const float* Wv        = (const float*)d_in[4];
    const float* Wo        = (const float*)d_in[5];
    float* out = (float*)d_out;

    float *q, *k, *v, *att, *xr, *wq, *wk, *wv, *wo;
    float2* rt;
    cudaGetSymbolAddress((void**)&q,   g_q);
    cudaGetSymbolAddress((void**)&k,   g_k);
    cudaGetSymbolAddress((void**)&v,   g_v);
    cudaGetSymbolAddress((void**)&att, g_att);
    cudaGetSymbolAddress((void**)&xr,  g_xr);
    cudaGetSymbolAddress((void**)&wq,  g_wq);
    cudaGetSymbolAddress((void**)&wk,  g_wk);
    cudaGetSymbolAddress((void**)&wv,  g_wv);
    cudaGetSymbolAddress((void**)&wo,  g_wo);
    cudaGetSymbolAddress((void**)&rt,  g_rt);

    cudaFuncSetAttribute(qkv_proj, cudaFuncAttributeMaxDynamicSharedMemorySize, GEMM_SMEM);
    cudaFuncSetAttribute(o_proj,   cudaFuncAttributeMaxDynamicSharedMemorySize, GEMM_SMEM);
    cudaFuncSetAttribute(flash_tc2, cudaFuncAttributeMaxDynamicSharedMemorySize, F2_SMEM);

    // Pre-round operands to tf32; build the sin/cos table
    {
        int nx = B_ * S_ * D_ / 4;
        round_tf32_kernel<<<(nx + 255) / 256, 256>>>(xr, x, nx);
        int nq = QH_ * D_ * HD_ / 4;
        round_tf32_kernel<<<(nq + 255) / 256, 256>>>(wq, Wq, nq);
        int nk = KH_ * D_ * HD_ / 4;
        round_tf32_kernel<<<(nk + 255) / 256, 256>>>(wk, Wk, nk);
        round_tf32_kernel<<<(nk + 255) / 256, 256>>>(wv, Wv, nk);
        int no = QH_ * HD_ * D_ / 4;
        round_tf32_kernel<<<(no + 255) / 256, 256>>>(wo, Wo, no);
        sincos_kernel<<<(S_ * 64 + 255) / 256, 256>>>(rt, positions);
    }

    // Merged QKV projection (Q/K written pair-permuted; V rounded)
    qkv_proj<<<dim3(QH_ + 2 * KH_, M_ROWS / 128), 256, GEMM_SMEM>>>(xr, wq, wk, wv, q, k, v);

    // RoPE in-place on permuted layout; Q absorbs the softmax scale
    {
        int tq = B_ * S_ * QH_ * (HD_ / 2);
        int tk = B_ * S_ * KH_ * (HD_ / 2);
        rope_kernel<<<(tq + 255) / 256, 256>>>(q, rt, QH_, tq, 0.08838834764831845f);
        rope_kernel<<<(tk + 255) / 256, 256>>>(k, rt, KH_, tk, 1.0f);
    }

    // Flash attention v3
    flash_tc2<<<dim3(S_ / 128, B_ * QH_), 512, F2_SMEM>>>(q, k, v, att);

    // Output projection
    o_proj<<<dim3(D_ / 128, M_ROWS / 128), 256, GEMM_SMEM>>>(att, wo, out);
}

// round 14
// speedup vs baseline: 1.0042x; 1.0042x over previous
#include <cuda_runtime.h>
#include <math.h>
#include <stdint.h>

// Problem dimensions (fixed by the dataset)
#define B_  2
#define S_  2048
#define D_  2048
#define QH_ 16
#define KH_ 4
#define HD_ 128
#define M_ROWS (B_ * S_)   // 4096

// ---------------------------------------------------------------------------
// Scratch (no allocations allowed -> __device__ globals)
// ---------------------------------------------------------------------------
__device__ float g_q[B_ * S_ * QH_ * HD_];   // 8M floats (pair-permuted cols)
__device__ float g_k[B_ * S_ * KH_ * HD_];   // 2M (pair-permuted cols)
__device__ float g_v[B_ * S_ * KH_ * HD_];   // 2M (natural)
__device__ float g_att[B_ * S_ * QH_ * HD_]; // 8M
__device__ float g_xr[B_ * S_ * D_];         // 8M  (tf32-rounded x)
__device__ float g_wq[QH_ * D_ * HD_];       // 4M  (tf32-rounded weights)
__device__ float g_wk[KH_ * D_ * HD_];       // 1M
__device__ float g_wv[KH_ * D_ * HD_];       // 1M
__device__ float g_wo[QH_ * HD_ * D_];       // 4M
__device__ float2 g_rt[S_ * 64];             // sin/cos table

// ---------------------------------------------------------------------------
// TF32 / cp.async helpers
// ---------------------------------------------------------------------------
__device__ __forceinline__ uint32_t f2tf32(float f) {
    uint32_t u;
    asm("cvt.rna.tf32.f32 %0, %1;" : "=r"(u) : "f"(f));
    return u;
}

__device__ __forceinline__ void mma_tf32(float* c, const uint32_t* a, const uint32_t* b) {
    asm volatile(
        "mma.sync.aligned.m16n8k8.row.col.f32.tf32.tf32.f32 "
        "{%0,%1,%2,%3}, {%4,%5,%6,%7}, {%8,%9}, {%0,%1,%2,%3};\n"
        : "+f"(c[0]), "+f"(c[1]), "+f"(c[2]), "+f"(c[3])
        : "r"(a[0]), "r"(a[1]), "r"(a[2]), "r"(a[3]), "r"(b[0]), "r"(b[1]));
}

__device__ __forceinline__ void cp_async16(void* sptr, const void* gptr) {
    uint32_t sa = (uint32_t)__cvta_generic_to_shared(sptr);
    asm volatile("cp.async.cg.shared.global [%0], [%1], 16;\n" :: "r"(sa), "l"(gptr));
}
#define CP_COMMIT() asm volatile("cp.async.commit_group;\n" ::: "memory")
#define CP_WAIT1()  asm volatile("cp.async.wait_group 1;\n" ::: "memory")

// pair permutation within an 8-group: j -> 2*(j&3) | (j>>2)
__device__ __forceinline__ int perm8(int j) { return (((j) & 3) << 1) | (((j) >> 2) & 1); }

// ---------------------------------------------------------------------------
// Elementwise tf32 rounding pass (vectorized)
// ---------------------------------------------------------------------------
__global__ void round_tf32_kernel(float* __restrict__ dst, const float* __restrict__ src,
                                  int n4) {
    int i = blockIdx.x * blockDim.x + threadIdx.x;
    if (i >= n4) return;
    float4 v = ((const float4*)src)[i];
    uint4 t = make_uint4(f2tf32(v.x), f2tf32(v.y), f2tf32(v.z), f2tf32(v.w));
    ((uint4*)dst)[i] = t;
}

// ---------------------------------------------------------------------------
// Pipelined TF32 GEMM body. CTA tile 128x128, BK=32, 3-stage cp.async.
// 256 threads = 8 warps (2m x 4n), warp tile 64x32, m16n8k8.
// acc = 64 regs/thread -> fits 2 CTAs/SM with __launch_bounds__(256, 2).
// PERMC: epilogue stores columns pair-permuted within 8-groups (Q/K outputs).
// ROUNDC: epilogue rounds C to tf32 (V output).
// ---------------------------------------------------------------------------
#define GSTAGES 3
#define ASTG (128 * 36)
#define BSTG (32 * 136)
#define STG_WORDS (ASTG + BSTG)
#define GEMM_SMEM (GSTAGES * STG_WORDS * 4)

template <bool PERMC, bool ROUNDC>
__device__ __forceinline__ void gemm_body(const float* __restrict__ A,
                                          const float* __restrict__ W,
                                          float* __restrict__ C,
                                          int K, int ldc, int wld,
                                          int brow, int ccol, float* smem) {
    const int tid  = threadIdx.x;
    const int lane = tid & 31;
    const int wid  = tid >> 5;
    const int warpm = wid >> 2;        // 0..1 (64-row slices)
    const int warpn = wid & 3;         // 0..3 (32-col slices)
    const int g = lane >> 2;
    const int q = lane & 3;

    const int am  = tid >> 3;          // 0..31
    const int ak4 = (tid & 7) << 2;    // 0..28
    const int bk  = tid >> 5;          // 0..7
    const int bn4 = (tid & 31) << 2;   // 0..124
    const int NITER = K >> 5;

    const float* Abase = A + (size_t)(brow + am) * K + ak4;

    float acc[4][4][4];
#pragma unroll
    for (int mt = 0; mt < 4; mt++)
#pragma unroll
        for (int nt = 0; nt < 4; nt++)
#pragma unroll
            for (int i = 0; i < 4; i++) acc[mt][nt][i] = 0.f;

    auto issue_tile = [&](int t) {
        float* As = smem + (t % GSTAGES) * STG_WORDS;
        float* Bs = As + ASTG;
        const int k0 = t << 5;
        const float* ap = Abase + k0;
#pragma unroll
        for (int p = 0; p < 4; p++)
            cp_async16(As + (am + 32 * p) * 36 + ak4, ap + (size_t)(32 * p) * K);
        const float* wp = W + (size_t)(k0 + bk) * wld + bn4;
#pragma unroll
        for (int p = 0; p < 4; p++)
            cp_async16(Bs + (bk + 8 * p) * 136 + bn4, wp + (size_t)(8 * p) * wld);
    };

    issue_tile(0); CP_COMMIT();
    issue_tile(1); CP_COMMIT();

    for (int i = 0; i < NITER; i++) {
        CP_WAIT1();
        __syncthreads();
        if (i + 2 < NITER) issue_tile(i + 2);
        CP_COMMIT();

        const uint32_t* As = (const uint32_t*)(smem + (i % GSTAGES) * STG_WORDS);
        const uint32_t* Bs = As + ASTG;

#pragma unroll
        for (int kk = 0; kk < 4; kk++) {
            const int kc = kk * 8;
            uint32_t af[4][4];
            uint32_t bf[4][2];
#pragma unroll
            for (int mt = 0; mt < 4; mt++) {
                int r = warpm * 64 + mt * 16 + g;
                af[mt][0] = As[r * 36 + kc + q];
                af[mt][1] = As[(r + 8) * 36 + kc + q];
                af[mt][2] = As[r * 36 + kc + q + 4];
                af[mt][3] = As[(r + 8) * 36 + kc + q + 4];
            }
#pragma unroll
            for (int nt = 0; nt < 4; nt++) {
                int c = warpn * 32 + nt * 8 + g;
                bf[nt][0] = Bs[(kc + q) * 136 + c];
                bf[nt][1] = Bs[(kc + q + 4) * 136 + c];
            }
#pragma unroll
            for (int mt = 0; mt < 4; mt++)
#pragma unroll
                for (int nt = 0; nt < 4; nt++)
                    mma_tf32(acc[mt][nt], af[mt], bf[nt]);
        }
    }

    // ---- epilogue ----
    const int p0 = perm8(2 * q);
    const int p1 = perm8(2 * q + 1);
#pragma unroll
    for (int mt = 0; mt < 4; mt++) {
        int r = brow + warpm * 64 + mt * 16 + g;
#pragma unroll
        for (int nt = 0; nt < 4; nt++) {
            if (PERMC) {
                int cb = ccol + warpn * 32 + nt * 8;
                C[(size_t)r * ldc + cb + p0] = acc[mt][nt][0];
                C[(size_t)r * ldc + cb + p1] = acc[mt][nt][1];
                C[(size_t)(r + 8) * ldc + cb + p0] = acc[mt][nt][2];
                C[(size_t)(r + 8) * ldc + cb + p1] = acc[mt][nt][3];
            } else {
                int c = ccol + warpn * 32 + nt * 8 + 2 * q;
                if (ROUNDC) {
                    uint2 c0 = make_uint2(f2tf32(acc[mt][nt][0]), f2tf32(acc[mt][nt][1]));
                    uint2 c1 = make_uint2(f2tf32(acc[mt][nt][2]), f2tf32(acc[mt][nt][3]));
                    *(uint2*)&C[(size_t)r * ldc + c] = c0;
                    *(uint2*)&C[(size_t)(r + 8) * ldc + c] = c1;
                } else {
                    *(float2*)&C[(size_t)r * ldc + c] = make_float2(acc[mt][nt][0], acc[mt][nt][1]);
                    *(float2*)&C[(size_t)(r + 8) * ldc + c] = make_float2(acc[mt][nt][2], acc[mt][nt][3]);
                }
            }
        }
    }
}

// Merged QKV projection: grid (24 head blocks, 32 row-blocks)
__global__ __launch_bounds__(256, 2) void qkv_proj(const float* __restrict__ x,
                                                   const float* __restrict__ Wq,
                                                   const float* __restrict__ Wk,
                                                   const float* __restrict__ Wv,
                                                   float* __restrict__ qo,
                                                   float* __restrict__ ko,
                                                   float* __restrict__ vo) {
    extern __shared__ float sm_f[];
    const int h = blockIdx.x;
    const int brow = blockIdx.y * 128;
    if (h < QH_) {
        gemm_body<true, false>(x, Wq + (size_t)h * D_ * HD_, qo,
                               D_, QH_ * HD_, HD_, brow, h * HD_, sm_f);
    } else if (h < QH_ + KH_) {
        int p = h - QH_;
        gemm_body<true, false>(x, Wk + (size_t)p * D_ * HD_, ko,
                               D_, KH_ * HD_, HD_, brow, p * HD_, sm_f);
    } else {
        int p = h - QH_ - KH_;
        gemm_body<false, true>(x, Wv + (size_t)p * D_ * HD_, vo,
                               D_, KH_ * HD_, HD_, brow, p * HD_, sm_f);
    }
}

// Output projection: grid (16 col-blocks of 128, 32 row-blocks)
__global__ __launch_bounds__(256, 2) void o_proj(const float* __restrict__ att,
                                                 const float* __restrict__ Wo,
                                                 float* __restrict__ out) {
    extern __shared__ float sm_f[];
    const int bcol = blockIdx.x * 128;
    const int brow = blockIdx.y * 128;
    gemm_body<false, false>(att, Wo + bcol, out, QH_ * HD_, D_, D_, brow, bcol, sm_f);
}

// ---------------------------------------------------------------------------
// sin/cos table: rt[s][hp] = (cos(ang), sin(ang)) — bit-identical ops
// ---------------------------------------------------------------------------
__global__ void sincos_kernel(float2* __restrict__ rt, const int* __restrict__ positions) {
    int i = blockIdx.x * blockDim.x + threadIdx.x;
    if (i >= S_ * 64) return;
    int hp = i & 63;
    int s  = i >> 6;
    float pos = (float)positions[s];
    float ts  = expf(((float)hp / 64.f) * 9.21034037197618f /* ln(1e4) */);
    float ang = pos / ts;
    rt[i] = make_float2(cosf(ang), sinf(ang));
}

// ---------------------------------------------------------------------------
// RoPE (in-place) on pair-permuted [B, S, NH, 128]; folds `scale` into the
// rotation (Q gets 1/sqrt(d), K gets 1). Each thread owns its 2 physical slots.
// ---------------------------------------------------------------------------
__global__ void rope_kernel(float* __restrict__ x, const float2* __restrict__ rt,
                            int NH, int total, float scale) {
    int i = blockIdx.x * blockDim.x + threadIdx.x;
    if (i >= total) return;
    int hp = i & 63;
    int rest = i >> 6;
    int nh = rest % NH;
    int s  = (rest / NH) % S_;
    int b  = rest / (NH * S_);

    float2 cs2 = rt[s * 64 + hp];
    float cs = cs2.x * scale;
    float sn = cs2.y * scale;

    int p = (hp & ~7) | perm8(hp & 7);
    size_t base = ((size_t)(b * S_ + s) * NH + nh) * HD_;
    float x1 = x[base + p];
    float x2 = x[base + p + 64];
    x[base + p]      = __uint_as_float(f2tf32(x1 * cs - x2 * sn));
    x[base + p + 64] = __uint_as_float(f2tf32(x2 * cs + x1 * sn));
}

// ---------------------------------------------------------------------------
// Flash attention v3 (unchanged from R10, passing @ ~380us)
// ---------------------------------------------------------------------------
#define QS2 136
#define KS2 136
#define VS2 136
#define PS2 72
#define KTILE_W (64 * KS2)

#define F2_SMEM ((128 * QS2 + 2 * KTILE_W + 64 * VS2 + 128 * PS2 + 512 + 512) * 4)

__global__ __launch_bounds__(512) void flash_tc2(const float* __restrict__ Q,
                                                 const float* __restrict__ K,
                                                 const float* __restrict__ V,
                                                 float* __restrict__ O) {
    extern __shared__ uint32_t sm_u[];
    uint32_t* Qs = sm_u;                    // [128][136] pair layout
    uint32_t* Kb = Qs + 128 * QS2;          // 2 x [64][136] pair layout
    uint32_t* Vs = Kb + 2 * KTILE_W;        // [64][136] natural
    uint32_t* Ps = Vs + 64 * VS2;           // [128][72] pair layout
    float* smax  = (float*)(Ps + 128 * PS2);   // [4][128]
    float* ssum  = smax + 512;                 // [4][128]

    const int tid  = threadIdx.x;
    const int lane = tid & 31;
    const int wid  = tid >> 5;
    const int warpm = wid >> 2;
    const int warpn = wid & 3;
    const int g = lane >> 2;
    const int q = lane & 3;

    const int mblk = gridDim.x - 1 - blockIdx.x;
    const int bq = blockIdx.y;
    const int b  = bq / QH_;
    const int qh = bq % QH_;
    const int kvh = qh / (QH_ / KH_);

    float rmr[2][2], rlr[2][2];
#pragma unroll
    for (int mt = 0; mt < 2; mt++)
#pragma unroll
        for (int h = 0; h < 2; h++) { rmr[mt][h] = -INFINITY; rlr[mt][h] = 0.f; }

    float o[2][4][4];
#pragma unroll
    for (int mt = 0; mt < 2; mt++)
#pragma unroll
        for (int nt = 0; nt < 4; nt++)
#pragma unroll
            for (int i = 0; i < 4; i++) o[mt][nt][i] = 0.f;

    const int row_base = warpm * 32 + g;
    const int qkcol_base = warpn * 16 + 2 * q;
    const int NIT = 2 * mblk + 2;

    auto issueQ = [&]() {
        for (int idx = tid; idx < 128 * 32; idx += 512) {
            int r  = idx >> 5;
            int c4 = (idx & 31) << 2;
            cp_async16(Qs + r * QS2 + c4,
                       Q + ((size_t)(b * S_ + mblk * 128 + r) * QH_ + qh) * HD_ + c4);
        }
    };
    auto issueK = [&](int n) {
        uint32_t* kd = Kb + (n & 1) * KTILE_W;
        for (int idx = tid; idx < 64 * 32; idx += 512) {
            int r  = idx >> 5;
            int c4 = (idx & 31) << 2;
            cp_async16(kd + r * KS2 + c4,
                       K + ((size_t)(b * S_ + n * 64 + r) * KH_ + kvh) * HD_ + c4);
        }
    };
    auto issueV = [&](int n) {
        for (int idx = tid; idx < 64 * 32; idx += 512) {
            int r  = idx >> 5;
            int c4 = (idx & 31) << 2;
            cp_async16(Vs + r * VS2 + c4,
                       V + ((size_t)(b * S_ + n * 64 + r) * KH_ + kvh) * HD_ + c4);
        }
    };

    issueQ(); issueK(0); issueV(0); CP_COMMIT();

    for (int n = 0; n < NIT; n++) {
        if (n + 1 < NIT) issueK(n + 1);
        CP_COMMIT();
        CP_WAIT1();
        __syncthreads();           // A: Q(first), K(n), V(n) ready

        const uint32_t* Kst = Kb + (n & 1) * KTILE_W;

        // ---- QK^T (scores pre-scaled via Q) ----
        float s[2][2][4];
#pragma unroll
        for (int mt = 0; mt < 2; mt++)
#pragma unroll
            for (int nt = 0; nt < 2; nt++)
#pragma unroll
                for (int i = 0; i < 4; i++) s[mt][nt][i] = 0.f;

#pragma unroll
        for (int ks = 0; ks < 16; ks++) {
            const int kc = ks * 8;
            uint32_t af[2][4], bf[2][2];
#pragma unroll
            for (int mt = 0; mt < 2; mt++) {
                int r = warpm * 32 + mt * 16 + g;
                uint2 a0 = *(const uint2*)&Qs[r * QS2 + kc + q * 2];
                uint2 a1 = *(const uint2*)&Qs[(r + 8) * QS2 + kc + q * 2];
                af[mt][0] = a0.x; af[mt][2] = a0.y;
                af[mt][1] = a1.x; af[mt][3] = a1.y;
            }
#pragma unroll
            for (int nt = 0; nt < 2; nt++) {
                int c = warpn * 16 + nt * 8 + g;
                uint2 b2 = *(const uint2*)&Kst[c * KS2 + kc + q * 2];
                bf[nt][0] = b2.x;
                bf[nt][1] = b2.y;
            }
#pragma unroll
            for (int mt = 0; mt < 2; mt++)
#pragma unroll
                for (int nt = 0; nt < 2; nt++)
                    mma_tf32(s[mt][nt], af[mt], bf[nt]);
        }

        // ---- causal mask (only on the diagonal pair of tiles) ----
        if (n >= 2 * mblk) {
            const int gr_base = mblk * 128 + row_base;
            const int gc_base = n * 64 + qkcol_base;
#pragma unroll
            for (int mt = 0; mt < 2; mt++) {
                int gr0 = gr_base + mt * 16;
                int gr1 = gr0 + 8;
#pragma unroll
                for (int nt = 0; nt < 2; nt++) {
                    int gc0 = gc_base + nt * 8;
                    int gc1 = gc0 + 1;
                    if (gc0 > gr0) s[mt][nt][0] = -1e9f;
                    if (gc1 > gr0) s[mt][nt][1] = -1e9f;
                    if (gc0 > gr1) s[mt][nt][2] = -1e9f;
                    if (gc1 > gr1) s[mt][nt][3] = -1e9f;
                }
            }
        }

        // ---- partial row max -> smax ----
#pragma unroll
        for (int mt = 0; mt < 2; mt++)
#pragma unroll
            for (int h = 0; h < 2; h++) {
                float pm = fmaxf(fmaxf(s[mt][0][2 * h], s[mt][0][2 * h + 1]),
                                 fmaxf(s[mt][1][2 * h], s[mt][1][2 * h + 1]));
                pm = fmaxf(pm, __shfl_xor_sync(0xFFFFFFFF, pm, 1));
                pm = fmaxf(pm, __shfl_xor_sync(0xFFFFFFFF, pm, 2));
                if (q == 0) smax[warpn * 128 + row_base + mt * 16 + 8 * h] = pm;
            }
        __syncthreads();           // B: smax complete

        // ---- m update (registers), exp, P store, partial sums ----
        const int poff0 = perm8(2 * q);
        const int poff1 = perm8(2 * q + 1);
        float corr[2][2];
#pragma unroll
        for (int mt = 0; mt < 2; mt++)
#pragma unroll
            for (int h = 0; h < 2; h++) {
                int row = row_base + mt * 16 + 8 * h;
                float m_tile = fmaxf(fmaxf(smax[row], smax[128 + row]),
                                     fmaxf(smax[256 + row], smax[384 + row]));
                float m_old = rmr[mt][h];
                float m_new = fmaxf(m_old, m_tile);
                corr[mt][h] = __expf(m_old - m_new);
                rmr[mt][h] = m_new;

                float psum = 0.f;
#pragma unroll
                for (int nt = 0; nt < 2; nt++) {
                    float p0 = __expf(s[mt][nt][2 * h] - m_new);
                    float p1 = __expf(s[mt][nt][2 * h + 1] - m_new);
                    psum += p0 + p1;
                    uint32_t* pb = Ps + row * PS2 + (warpn * 2 + nt) * 8;
                    pb[poff0] = f2tf32(p0);
                    pb[poff1] = f2tf32(p1);
                }
                psum += __shfl_xor_sync(0xFFFFFFFF, psum, 1);
                psum += __shfl_xor_sync(0xFFFFFFFF, psum, 2);
                if (q == 0) ssum[warpn * 128 + row] = psum;
            }
        __syncthreads();           // C: Ps + ssum complete

        // ---- l update (registers) ----
#pragma unroll
        for (int mt = 0; mt < 2; mt++)
#pragma unroll
            for (int h = 0; h < 2; h++) {
                int row = row_base + mt * 16 + 8 * h;
                float ts = ssum[row] + ssum[128 + row] + ssum[256 + row] + ssum[384 + row];
                rlr[mt][h] = rlr[mt][h] * corr[mt][h] + ts;
            }

        // ---- rescale O, then PV mma ----
#pragma unroll
        for (int mt = 0; mt < 2; mt++)
#pragma unroll
            for (int nt = 0; nt < 4; nt++) {
                o[mt][nt][0] *= corr[mt][0];
                o[mt][nt][1] *= corr[mt][0];
                o[mt][nt][2] *= corr[mt][1];
                o[mt][nt][3] *= corr[mt][1];
            }

#pragma unroll
        for (int ks = 0; ks < 8; ks++) {
            const int kc = ks * 8;
            uint32_t af[2][4], bf[4][2];
#pragma unroll
            for (int mt = 0; mt < 2; mt++) {
                int r = warpm * 32 + mt * 16 + g;
                uint2 a0 = *(const uint2*)&Ps[r * PS2 + kc + q * 2];
                uint2 a1 = *(const uint2*)&Ps[(r + 8) * PS2 + kc + q * 2];
                af[mt][0] = a0.x; af[mt][2] = a0.y;
                af[mt][1] = a1.x; af[mt][3] = a1.y;
            }
#pragma unroll
            for (int nt = 0; nt < 4; nt++) {
                int c = warpn * 32 + nt * 8 + g;
                bf[nt][0] = Vs[(kc + q) * VS2 + c];
                bf[nt][1] = Vs[(kc + q + 4) * VS2 + c];
            }
#pragma unroll
            for (int mt = 0; mt < 2; mt++)
#pragma unroll
                for (int nt = 0; nt < 4; nt++)
                    mma_tf32(o[mt][nt], af[mt], bf[nt]);
        }

        __syncthreads();           // D: all warps done with Ps/Vs
        if (n + 1 < NIT) issueV(n + 1);
        CP_COMMIT();
    }

    // ---- epilogue: normalize + round to tf32 (o_proj consumes raw) ----
#pragma unroll
    for (int mt = 0; mt < 2; mt++) {
        float inv0 = 1.0f / rlr[mt][0];
        float inv1 = 1.0f / rlr[mt][1];
        int s0 = mblk * 128 + row_base + mt * 16;
#pragma unroll
        for (int nt = 0; nt < 4; nt++) {
            int col = warpn * 32 + nt * 8 + 2 * q;
            float* op0 = O + ((size_t)(b * S_ + s0) * QH_ + qh) * HD_ + col;
            float* op1 = O + ((size_t)(b * S_ + s0 + 8) * QH_ + qh) * HD_ + col;
            *(uint2*)op0 = make_uint2(f2tf32(o[mt][nt][0] * inv0), f2tf32(o[mt][nt][1] * inv0));
            *(uint2*)op1 = make_uint2(f2tf32(o[mt][nt][2] * inv1), f2tf32(o[mt][nt][3] * inv1));
        }
    }
}

// ---------------------------------------------------------------------------
// Launch
// ---------------------------------------------------------------------------
extern "C" void kernel_launch(void* const* d_in, const int* in_sizes, int n_in,
                              void* d_out, int out_size) {
    const float* x         = (const float*)d_in[0];
    const int*   positions = (const int*)d_in[1];
    const float* Wq        = (const float*)d_in[2];
    const float* Wk        = (const float*)d_in[3];
    const float* Wv        = (const float*)d_in[4];
    const float* Wo        = (const float*)d_in[5];
    float* out = (float*)d_out;

    float *q, *k, *v, *att, *xr, *wq, *wk, *wv, *wo;
    float2* rt;
    cudaGetSymbolAddress((void**)&q,   g_q);
    cudaGetSymbolAddress((void**)&k,   g_k);
    cudaGetSymbolAddress((void**)&v,   g_v);
    cudaGetSymbolAddress((void**)&att, g_att);
    cudaGetSymbolAddress((void**)&xr,  g_xr);
    cudaGetSymbolAddress((void**)&wq,  g_wq);
    cudaGetSymbolAddress((void**)&wk,  g_wk);
    cudaGetSymbolAddress((void**)&wv,  g_wv);
    cudaGetSymbolAddress((void**)&wo,  g_wo);
    cudaGetSymbolAddress((void**)&rt,  g_rt);

    cudaFuncSetAttribute(qkv_proj, cudaFuncAttributeMaxDynamicSharedMemorySize, GEMM_SMEM);
    cudaFuncSetAttribute(o_proj,   cudaFuncAttributeMaxDynamicSharedMemorySize, GEMM_SMEM);
    cudaFuncSetAttribute(flash_tc2, cudaFuncAttributeMaxDynamicSharedMemorySize, F2_SMEM);

    // Pre-round operands to tf32; build the sin/cos table
    {
        int nx = B_ * S_ * D_ / 4;
        round_tf32_kernel<<<(nx + 255) / 256, 256>>>(xr, x, nx);
        int nq = QH_ * D_ * HD_ / 4;
        round_tf32_kernel<<<(nq + 255) / 256, 256>>>(wq, Wq, nq);
        int nk = KH_ * D_ * HD_ / 4;
        round_tf32_kernel<<<(nk + 255) / 256, 256>>>(wk, Wk, nk);
        round_tf32_kernel<<<(nk + 255) / 256, 256>>>(wv, Wv, nk);
        int no = QH_ * HD_ * D_ / 4;
        round_tf32_kernel<<<(no + 255) / 256, 256>>>(wo, Wo, no);
        sincos_kernel<<<(S_ * 64 + 255) / 256, 256>>>(rt, positions);
    }

    // Merged QKV projection (Q/K written pair-permuted; V rounded)
    qkv_proj<<<dim3(QH_ + 2 * KH_, M_ROWS / 128), 256, GEMM_SMEM>>>(xr, wq, wk, wv, q, k, v);

    // RoPE in-place on permuted layout; Q absorbs the softmax scale
    {
        int tq = B_ * S_ * QH_ * (HD_ / 2);
        int tk = B_ * S_ * KH_ * (HD_ / 2);
        rope_kernel<<<(tq + 255) / 256, 256>>>(q, rt, QH_, tq, 0.08838834764831845f);
        rope_kernel<<<(tk + 255) / 256, 256>>>(k, rt, KH_, tk, 1.0f);
    }

    // Flash attention v3
    flash_tc2<<<dim3(S_ / 128, B_ * QH_), 512, F2_SMEM>>>(q, k, v, att);

    // Output projection
    o_proj<<<dim3(D_ / 128, M_ROWS / 128), 256, GEMM_SMEM>>>(att, wo, out);
}